// round 9
// baseline (speedup 1.0000x reference)
#include <cuda_runtime.h>
#include <cuda_bf16.h>
#include <cuda_fp16.h>
#include <cstdint>
#include <cstddef>

// ---------------------------------------------------------------------------
// DSDModules via mma.sync bf16 m16n8k16. v6: 8-warp CTAs (4M x 2N, 32-row
// warp tiles) -> 2x warps/SM at constant smem-fragment traffic; PRELOAD path
// for CIN=64 convs; single-sync multistage loop for conv1/2; tap-dedup
// deformable gather.
// ---------------------------------------------------------------------------

#define NP 4096

// ---- scratch offsets (float units) -----------------------------------------
#define OFF_INT  0ull            // inTb  [4096][512]  bf16
#define OFF_GART 1048576ull      // garTh [4096][256]  fp16
#define OFF_WB1  1572864ull      // wb1   [8][128][4608] bf16
#define OFF_WB2  3932160ull      // wb2   [8][64][1152]  bf16
#define OFF_WB3  4227072ull      // wb3   [8][32][576]   bf16
#define OFF_WB4  4300800ull      // wb4   [8][32][576]   bf16 (cin-padded)
#define OFF_H1   4374528ull      // h1 [8][4096][128] bf16
#define OFF_H2   6471680ull      // h2 [8][4096][64]  bf16
#define OFF_H3   7520256ull      // h3 [8][4096][64]  bf16 (upper 32 stay 0)
#define OFF_OA   8568832ull      // oa [8][18][4096]  fp32
#define SCRATCH_FLOATS 9158656ull

__device__ __align__(1024) float g_scratch[SCRATCH_FLOATS];

// ---- helpers ---------------------------------------------------------------
__device__ __forceinline__ uint32_t smem_u32(const void* p) {
    uint32_t a;
    asm("{ .reg .u64 t; cvta.to.shared.u64 t, %1; cvt.u32.u64 %0, t; }"
        : "=r"(a) : "l"(p));
    return a;
}
__device__ __forceinline__ void cp16(uint32_t sa, const void* g, bool ok) {
    int sz = ok ? 16 : 0;
    asm volatile("cp.async.cg.shared.global [%0], [%1], 16, %2;"
                 :: "r"(sa), "l"(g), "r"(sz) : "memory");
}
#define CP_COMMIT() asm volatile("cp.async.commit_group;" ::: "memory")
#define CP_WAIT(n)  asm volatile("cp.async.wait_group %0;" :: "n"(n) : "memory")

__device__ __forceinline__ void ldsm4(uint32_t* r, uint32_t addr) {
    asm volatile("ldmatrix.sync.aligned.m8n8.x4.shared.b16 {%0,%1,%2,%3}, [%4];"
                 : "=r"(r[0]), "=r"(r[1]), "=r"(r[2]), "=r"(r[3]) : "r"(addr));
}
__device__ __forceinline__ void mma_bf16(float* c, const uint32_t* a, const uint32_t* b) {
    asm volatile(
        "mma.sync.aligned.m16n8k16.row.col.f32.bf16.bf16.f32 "
        "{%0,%1,%2,%3}, {%4,%5,%6,%7}, {%8,%9}, {%0,%1,%2,%3};"
        : "+f"(c[0]), "+f"(c[1]), "+f"(c[2]), "+f"(c[3])
        : "r"(a[0]), "r"(a[1]), "r"(a[2]), "r"(a[3]), "r"(b[0]), "r"(b[1]));
}

// ---------------------------------------------------------------------------
// Fused prep kernel: transpose + all 4 weight reorders.
// ---------------------------------------------------------------------------
__device__ void wb_region(const float* __restrict__ W, __nv_bfloat16* __restrict__ Wb,
                          int CINR, int CINP, int COUTR, int COUTP,
                          size_t tidg, size_t nthreads) {
    int K = CINP * 9;
    size_t total = (size_t)8 * COUTP * K;
    for (size_t i = tidg; i < total; i += nthreads) {
        int k = (int)(i % K);
        size_t rem = i / K;
        int m = (int)(rem % COUTP);
        int g = (int)(rem / COUTP);
        int tap = k / CINP, cin = k - tap * CINP;
        float v = 0.f;
        if (m < COUTR && cin < CINR)
            v = W[((size_t)(g * COUTR + m) * CINR + cin) * 9 + tap];
        Wb[i] = __float2bfloat16_rn(v);
    }
}

__global__ __launch_bounds__(256)
void prep_all(const float* __restrict__ gar, const float* __restrict__ cond,
              __nv_bfloat16* __restrict__ inTb, __half* __restrict__ garTh,
              const float* __restrict__ W1, __nv_bfloat16* __restrict__ wb1,
              const float* __restrict__ W2, __nv_bfloat16* __restrict__ wb2,
              const float* __restrict__ W3, __nv_bfloat16* __restrict__ wb3,
              const float* __restrict__ W4, __nv_bfloat16* __restrict__ wb4) {
    if (blockIdx.x < 2048) {
        __shared__ float tile[32][33];
        int tx = threadIdx.x & 31;
        int ty = threadIdx.x >> 5;
        int p0 = (blockIdx.x & 127) * 32;
        int c0 = (blockIdx.x >> 7) * 32;
        for (int i = ty; i < 32; i += 8) {
            int c = c0 + i;
            const float* src = (c < 256) ? (gar + (size_t)c * NP)
                                         : (cond + (size_t)(c - 256) * NP);
            tile[i][tx] = src[p0 + tx];
        }
        __syncthreads();
        for (int i = ty; i < 32; i += 8) {
            float v = tile[tx][i];
            int pix = p0 + i, c = c0 + tx;
            inTb[(size_t)pix * 512 + c] = __float2bfloat16_rn(v);
            if (c0 < 256)
                garTh[(size_t)pix * 256 + c] = __float2half_rn(v);
        }
    } else {
        size_t tidg = (size_t)(blockIdx.x - 2048) * 256 + threadIdx.x;
        size_t nt   = (size_t)2752 * 256;
        wb_region(W1, wb1, 512, 512, 128, 128, tidg, nt);
        wb_region(W2, wb2, 128, 128,  64,  64, tidg, nt);
        wb_region(W3, wb3,  64,  64,  32,  32, tidg, nt);
        wb_region(W4, wb4,  32,  64,  18,  32, tidg, nt);
    }
}

// ---------------------------------------------------------------------------
// bf16 band-reuse implicit-GEMM 3x3 conv. 256 threads = 8 warps (4M x 2N),
// warp tile 32 x (COUT/2). CTA: 128 px (2 image rows) x COUT.
//   NCC==1 (CIN=64): single band + ALL 9 B tap-chunks preloaded, no in-loop
//   barriers, 3 CTAs/SM. Else: double-buffered band + B, one barrier per
//   tap-chunk, next chunk's cp.async overlaps current chunk's MMAs.
// ---------------------------------------------------------------------------
template<int CIN, int COUT, int COUT_REAL, int OUT_STRIDE, bool RELU, int OUT_MODE, int MINB>
__global__ __launch_bounds__(256, MINB)
void mconv(const __nv_bfloat16* __restrict__ in, size_t gstride,
           const __nv_bfloat16* __restrict__ Wb, const float* __restrict__ bias,
           void* __restrict__ outv) {
    constexpr int  K       = CIN * 9;
    constexpr int  NCC     = CIN / 64;
    constexpr int  TOT     = NCC * 9;
    constexpr bool PRELOAD = (NCC == 1);
    constexpr int  WN      = COUT / 2;
    constexpr int  NTT     = WN / 8;
    constexpr int  BPIX    = 264;              // 4 rows x 66 cols
    constexpr int  BSTAGE  = BPIX * 128;       // band stage bytes
    constexpr int  BBS     = COUT * 128;       // B stage bytes
    constexpr int  NBAND   = PRELOAD ? 1 : 2;

    extern __shared__ char sm[];
    uint32_t dyn  = smem_u32(sm);
    uint32_t base = (dyn + 1023u) & ~1023u;

    const int tid  = threadIdx.x;
    const int warp = tid >> 5;
    const int lane = tid & 31;
    const int lq   = lane >> 2;
    const int lc   = lane & 3;
    const int wm   = warp & 3;                 // 4 M-warps (32 px each)
    const int wn   = warp >> 2;                // 2 N-warps
    const int tile = blockIdx.x;
    const int g    = blockIdx.y;
    const int y0   = tile * 2 - 1;

    const __nv_bfloat16* src = in + (size_t)g * gstride;
    const __nv_bfloat16* wg  = Wb + (size_t)g * COUT * K;

    const uint32_t bandBase = base;
    const uint32_t bbBase   = base + NBAND * BSTAGE;

    float acc[2][NTT][4];
    #pragma unroll
    for (int i = 0; i < 2; i++)
        #pragma unroll
        for (int j = 0; j < NTT; j++)
            #pragma unroll
            for (int q = 0; q < 4; q++) acc[i][j][q] = 0.f;

    auto band_load = [&](int cc, int buf) {
        int c0 = cc * 64;
        for (int it = tid; it < BPIX * 8; it += 256) {
            int bp = it >> 3, seg = it & 7;
            int br = bp / 66;
            int col = bp - br * 66;
            int y = y0 + br, x = col - 1;
            bool ok = ((unsigned)y < 64u) & ((unsigned)x < 64u);
            int pix = ok ? (y * 64 + x) : 0;
            const __nv_bfloat16* gp = src + (size_t)pix * CIN + c0 + seg * 8;
            cp16(bandBase + buf * BSTAGE
                 + (uint32_t)(bp * 128 + ((seg * 16) ^ ((bp & 7) * 16))), gp, ok);
        }
    };
    auto b_load = [&](int kc, int stage) {
        int cc = kc / 9;
        int koff = (kc - cc * 9) * CIN + cc * 64;
        for (int it = tid; it < COUT * 8; it += 256) {
            int m = it >> 3, seg = it & 7;
            const __nv_bfloat16* gp = wg + (size_t)m * K + koff + seg * 8;
            cp16(bbBase + stage * BBS
                 + (uint32_t)(m * 128 + ((seg * 16) ^ ((m & 7) * 16))), gp, true);
        }
    };

    // lane-constant ldmatrix address components (A fragments)
    const int amat  = lane >> 3;
    const int aroff = (lane & 7) + (amat & 1) * 8;
    const int akb   = (amat >> 1) * 16;

    auto compute = [&](int tap, int bandbuf, int bstage) {
        int r = tap / 3, s = tap - 3 * (tap / 3);
        // warp covers pixels (wm>>1)-th image row, (wm&1)-th 32-px half
        int bbase0 = ((wm >> 1) + r) * 66 + (wm & 1) * 32 + s;
        uint32_t aS = bandBase + bandbuf * BSTAGE;
        uint32_t bS = bbBase + bstage * BBS;
        #pragma unroll
        for (int seg = 0; seg < 4; seg++) {
            uint32_t af[2][4];
            #pragma unroll
            for (int mt = 0; mt < 2; mt++) {
                int bp = bbase0 + mt * 16 + aroff;
                uint32_t addr = aS + (uint32_t)(bp * 128 + ((seg * 32 + akb) ^ ((bp & 7) * 16)));
                ldsm4(af[mt], addr);
            }
            uint32_t bf[NTT][2];
            #pragma unroll
            for (int ntp = 0; ntp < NTT / 2; ntp++) {
                int n = wn * WN + (ntp * 2 + (lane >> 4)) * 8 + (lane & 7);
                int kb = ((lane >> 3) & 1) * 16;
                uint32_t addr = bS + (uint32_t)(n * 128 + ((seg * 32 + kb) ^ ((n & 7) * 16)));
                uint32_t tmp[4];
                ldsm4(tmp, addr);
                bf[2 * ntp][0] = tmp[0]; bf[2 * ntp][1] = tmp[1];
                bf[2 * ntp + 1][0] = tmp[2]; bf[2 * ntp + 1][1] = tmp[3];
            }
            #pragma unroll
            for (int mt = 0; mt < 2; mt++)
                #pragma unroll
                for (int nt = 0; nt < NTT; nt++)
                    mma_bf16(acc[mt][nt], af[mt], bf[nt]);
        }
    };

    if (PRELOAD) {
        band_load(0, 0);
        #pragma unroll
        for (int t9 = 0; t9 < 9; t9++) b_load(t9, t9);
        CP_COMMIT();
        CP_WAIT(0);
        __syncthreads();
        #pragma unroll
        for (int tap = 0; tap < 9; tap++)
            compute(tap, 0, tap);
    } else {
        band_load(0, 0); b_load(0, 0); CP_COMMIT();
        for (int kc = 0; kc < TOT; kc++) {
            CP_WAIT(0);
            __syncthreads();                  // all threads past compute(kc-1)
            int nb = kc + 1;
            if (nb < TOT) {                   // issue next loads, overlap compute
                if (nb % 9 == 0) band_load(nb / 9, (nb / 9) & 1);
                b_load(nb, nb & 1);
                CP_COMMIT();
            }
            int cc = kc / 9, tap = kc - cc * 9;
            compute(tap, cc & 1, kc & 1);
        }
    }

    // Epilogue: bias + lrelu, store.
    #pragma unroll
    for (int mt = 0; mt < 2; mt++) {
        int prow = tile * 128 + (wm >> 1) * 64 + (wm & 1) * 32 + mt * 16 + lq;
        #pragma unroll
        for (int nt = 0; nt < NTT; nt++) {
            int n0 = wn * WN + nt * 8 + lc * 2;
            float b0 = (n0     < COUT_REAL) ? bias[g * COUT_REAL + n0]     : 0.f;
            float b1 = (n0 + 1 < COUT_REAL) ? bias[g * COUT_REAL + n0 + 1] : 0.f;
            #pragma unroll
            for (int h = 0; h < 2; h++) {
                int p = prow + h * 8;
                float v0 = acc[mt][nt][h * 2]     + b0;
                float v1 = acc[mt][nt][h * 2 + 1] + b1;
                if (RELU) {
                    v0 = (v0 >= 0.f) ? v0 : 0.1f * v0;
                    v1 = (v1 >= 0.f) ? v1 : 0.1f * v1;
                }
                if (OUT_MODE == 0) {
                    __nv_bfloat16* ob = (__nv_bfloat16*)outv;
                    __nv_bfloat162 pr;
                    pr.x = __float2bfloat16_rn(v0);
                    pr.y = __float2bfloat16_rn(v1);
                    *(__nv_bfloat162*)(ob + ((size_t)g * NP + p) * OUT_STRIDE + n0) = pr;
                } else {
                    float* of = (float*)outv;
                    if (n0 < COUT_REAL)
                        of[(size_t)(g * COUT_REAL + n0) * NP + p] = v0;
                    if (n0 + 1 < COUT_REAL)
                        of[(size_t)(g * COUT_REAL + n0 + 1) * NP + p] = v1;
                }
            }
        }
    }
}

// ---------------------------------------------------------------------------
// Final warp/sample kernel with tap dedup (unchanged from v5).
// ---------------------------------------------------------------------------
__global__ __launch_bounds__(256)
void warp_kernel(const float* __restrict__ oa, const __half* __restrict__ garTh,
                 const float* __restrict__ mask, float* __restrict__ out) {
    __shared__ int   sO[4][192];
    __shared__ float sA[4][192];
    __shared__ int   sPosC[4][8][24];
    __shared__ float sWC[4][8][24];
    __shared__ int   sCnt[4][8];

    const int pix0 = blockIdx.x * 4;
    const int tt = threadIdx.x;

    if (tt < 24) {
        int p = tt / 6, k = tt - (tt / 6) * 6;
        int pix = pix0 + p;
        float fx = (float)(pix & 63);
        float fy = (float)(pix >> 6);
        float lg[8], ox[8], oy[8];
        #pragma unroll
        for (int g = 0; g < 8; g++) {
            const float* base = oa + (size_t)g * 18 * NP + pix;
            lg[g] = base[(12 + k) * NP];
            ox[g] = base[(2 * k) * NP];
            oy[g] = base[(2 * k + 1) * NP];
        }
        float m = lg[0];
        #pragma unroll
        for (int g = 1; g < 8; g++) m = fmaxf(m, lg[g]);
        float s = 0.f;
        #pragma unroll
        for (int g = 0; g < 8; g++) { lg[g] = expf(lg[g] - m); s += lg[g]; }
        float inv = 1.f / s;
        #pragma unroll
        for (int g = 0; g < 8; g++) {
            float attn = lg[g] * inv;
            float xs = fminf(fmaxf((fx + ox[g]) * (64.0f / 63.0f) - 0.5f, 0.f), 63.f);
            float ys = fminf(fmaxf((fy + oy[g]) * (64.0f / 63.0f) - 0.5f, 0.f), 63.f);
            float x0f = floorf(xs), y0f = floorf(ys);
            float wx = xs - x0f, wy = ys - y0f;
            int x0 = (int)x0f, y0 = (int)y0f;
            int x1 = min(x0 + 1, 63), y1 = min(y0 + 1, 63);
            int q = (p * 6 + k) * 8 + g;
            sO[0][q] = (y0 * 64 + x0) * 256;
            sO[1][q] = (y0 * 64 + x1) * 256;
            sO[2][q] = (y1 * 64 + x0) * 256;
            sO[3][q] = (y1 * 64 + x1) * 256;
            sA[0][q] = attn * (1.f - wy) * (1.f - wx);
            sA[1][q] = attn * (1.f - wy) * wx;
            sA[2][q] = attn * wy * (1.f - wx);
            sA[3][q] = attn * wy * wx;
        }
    }
    __syncthreads();

    if (tt < 32) {
        int p = tt >> 3, g = tt & 7;
        int cnt = 0;
        for (int k = 0; k < 6; k++) {
            int qbase = (p * 6 + k) * 8 + g;
            #pragma unroll
            for (int q = 0; q < 4; q++) {
                int   po = sO[q][qbase];
                float ww = sA[q][qbase];
                int j = 0;
                for (; j < cnt; j++) {
                    if (sPosC[p][g][j] == po) { sWC[p][g][j] += ww; break; }
                }
                if (j == cnt) { sPosC[p][g][cnt] = po; sWC[p][g][cnt] = ww; cnt++; }
            }
        }
        sCnt[p][g] = cnt;
    }
    __syncthreads();

    const int c = tt;  // channel
    float mk[8];
    #pragma unroll
    for (int g = 0; g < 8; g++) mk[g] = mask[g * 256 + c];

    for (int p = 0; p < 4; p++) {
        float accP = 0.f;
        #pragma unroll
        for (int g = 0; g < 8; g++) {
            int cnt = sCnt[p][g];      // uniform across block
            float accG = 0.f;
            for (int j = 0; j < cnt; j++)
                accG += sWC[p][g][j] * __half2float(garTh[sPosC[p][g][j] + c]);
            accP += accG * mk[g];
        }
        out[(size_t)c * NP + pix0 + p] = accP;
    }
}

// ---------------------------------------------------------------------------
extern "C" void kernel_launch(void* const* d_in, const int* in_sizes, int n_in,
                              void* d_out, int out_size) {
    const float* gar  = (const float*)d_in[0];
    const float* cond = (const float*)d_in[1];
    const float* mask = (const float*)d_in[2];
    const float* W1   = (const float*)d_in[3];
    const float* b1   = (const float*)d_in[4];
    const float* W2   = (const float*)d_in[5];
    const float* b2   = (const float*)d_in[6];
    const float* W3   = (const float*)d_in[7];
    const float* b3   = (const float*)d_in[8];
    const float* W4   = (const float*)d_in[9];
    const float* b4   = (const float*)d_in[10];
    float* out = (float*)d_out;

    float* S = nullptr;
    cudaGetSymbolAddress((void**)&S, g_scratch);
    __nv_bfloat16* inTb  = (__nv_bfloat16*)(S + OFF_INT);
    __half*        garTh = (__half*)       (S + OFF_GART);
    __nv_bfloat16* wb1   = (__nv_bfloat16*)(S + OFF_WB1);
    __nv_bfloat16* wb2   = (__nv_bfloat16*)(S + OFF_WB2);
    __nv_bfloat16* wb3   = (__nv_bfloat16*)(S + OFF_WB3);
    __nv_bfloat16* wb4   = (__nv_bfloat16*)(S + OFF_WB4);
    __nv_bfloat16* h1    = (__nv_bfloat16*)(S + OFF_H1);
    __nv_bfloat16* h2    = (__nv_bfloat16*)(S + OFF_H2);
    __nv_bfloat16* h3    = (__nv_bfloat16*)(S + OFF_H3);
    float*         oa    = S + OFF_OA;

    // dynamic smem
    const int SM1  = 2 * 264 * 128 + 2 * 128 * 128 + 1024;  // 101376
    const int SM2  = 2 * 264 * 128 + 2 * 64 * 128 + 1024;   //  84992
    const int SM34 = 1 * 264 * 128 + 9 * 32 * 128 + 1024;   //  71680

    cudaFuncSetAttribute(mconv<512,128,128,128,true ,0,2>, cudaFuncAttributeMaxDynamicSharedMemorySize, SM1);
    cudaFuncSetAttribute(mconv<128, 64, 64, 64,true ,0,2>, cudaFuncAttributeMaxDynamicSharedMemorySize, SM2);
    cudaFuncSetAttribute(mconv< 64, 32, 32, 64,true ,0,3>, cudaFuncAttributeMaxDynamicSharedMemorySize, SM34);
    cudaFuncSetAttribute(mconv< 64, 32, 18,  1,false,1,3>, cudaFuncAttributeMaxDynamicSharedMemorySize, SM34);

    prep_all<<<2048 + 2752, 256>>>(gar, cond, inTb, garTh,
                                   W1, wb1, W2, wb2, W3, wb3, W4, wb4);

    mconv<512,128,128,128,true ,0,2><<<dim3(32, 8), 256, SM1 >>>(inTb, 0,               wb1, b1, h1);
    mconv<128, 64, 64, 64,true ,0,2><<<dim3(32, 8), 256, SM2 >>>(h1, (size_t)NP * 128,  wb2, b2, h2);
    mconv< 64, 32, 32, 64,true ,0,3><<<dim3(32, 8), 256, SM34>>>(h2, (size_t)NP * 64,   wb3, b3, h3);
    mconv< 64, 32, 18,  1,false,1,3><<<dim3(32, 8), 256, SM34>>>(h3, (size_t)NP * 64,   wb4, b4, oa);

    warp_kernel<<<NP / 4, 256>>>(oa, garTh, mask, out);
}

// round 10
// speedup vs baseline: 1.0117x; 1.0117x over previous
#include <cuda_runtime.h>
#include <cuda_bf16.h>
#include <cuda_fp16.h>
#include <cstdint>
#include <cstddef>

// ---------------------------------------------------------------------------
// DSDModules via mma.sync bf16 m16n8k16. v7: grid-size-driven co-residency —
// cout-split conv1/conv2 (512 CTAs, single-buffered band, occ 4-5) and 1-row
// tiles for conv3/4 (512 CTAs, occ 6). One unified pipelined single-band
// loop; 2M x 2N warp geometry (minimal fragment duplication) everywhere.
// ---------------------------------------------------------------------------

#define NP 4096

// ---- scratch offsets (float units) -----------------------------------------
#define OFF_INT  0ull            // inTb  [4096][512]  bf16
#define OFF_GART 1048576ull      // garTh [4096][256]  fp16
#define OFF_WB1  1572864ull      // wb1   [8][128][4608] bf16
#define OFF_WB2  3932160ull      // wb2   [8][64][1152]  bf16
#define OFF_WB3  4227072ull      // wb3   [8][32][576]   bf16
#define OFF_WB4  4300800ull      // wb4   [8][32][576]   bf16 (cin-padded)
#define OFF_H1   4374528ull      // h1 [8][4096][128] bf16
#define OFF_H2   6471680ull      // h2 [8][4096][64]  bf16
#define OFF_H3   7520256ull      // h3 [8][4096][64]  bf16 (upper 32 stay 0)
#define OFF_OA   8568832ull      // oa [8][18][4096]  fp32
#define SCRATCH_FLOATS 9158656ull

__device__ __align__(1024) float g_scratch[SCRATCH_FLOATS];

// ---- helpers ---------------------------------------------------------------
__device__ __forceinline__ uint32_t smem_u32(const void* p) {
    uint32_t a;
    asm("{ .reg .u64 t; cvta.to.shared.u64 t, %1; cvt.u32.u64 %0, t; }"
        : "=r"(a) : "l"(p));
    return a;
}
__device__ __forceinline__ void cp16(uint32_t sa, const void* g, bool ok) {
    int sz = ok ? 16 : 0;
    asm volatile("cp.async.cg.shared.global [%0], [%1], 16, %2;"
                 :: "r"(sa), "l"(g), "r"(sz) : "memory");
}
#define CP_COMMIT() asm volatile("cp.async.commit_group;" ::: "memory")
#define CP_WAIT(n)  asm volatile("cp.async.wait_group %0;" :: "n"(n) : "memory")

__device__ __forceinline__ void ldsm4(uint32_t* r, uint32_t addr) {
    asm volatile("ldmatrix.sync.aligned.m8n8.x4.shared.b16 {%0,%1,%2,%3}, [%4];"
                 : "=r"(r[0]), "=r"(r[1]), "=r"(r[2]), "=r"(r[3]) : "r"(addr));
}
__device__ __forceinline__ void mma_bf16(float* c, const uint32_t* a, const uint32_t* b) {
    asm volatile(
        "mma.sync.aligned.m16n8k16.row.col.f32.bf16.bf16.f32 "
        "{%0,%1,%2,%3}, {%4,%5,%6,%7}, {%8,%9}, {%0,%1,%2,%3};"
        : "+f"(c[0]), "+f"(c[1]), "+f"(c[2]), "+f"(c[3])
        : "r"(a[0]), "r"(a[1]), "r"(a[2]), "r"(a[3]), "r"(b[0]), "r"(b[1]));
}

// ---------------------------------------------------------------------------
// Fused prep kernel: transpose + all 4 weight reorders.
// ---------------------------------------------------------------------------
__device__ void wb_region(const float* __restrict__ W, __nv_bfloat16* __restrict__ Wb,
                          int CINR, int CINP, int COUTR, int COUTP,
                          size_t tidg, size_t nthreads) {
    int K = CINP * 9;
    size_t total = (size_t)8 * COUTP * K;
    for (size_t i = tidg; i < total; i += nthreads) {
        int k = (int)(i % K);
        size_t rem = i / K;
        int m = (int)(rem % COUTP);
        int g = (int)(rem / COUTP);
        int tap = k / CINP, cin = k - tap * CINP;
        float v = 0.f;
        if (m < COUTR && cin < CINR)
            v = W[((size_t)(g * COUTR + m) * CINR + cin) * 9 + tap];
        Wb[i] = __float2bfloat16_rn(v);
    }
}

__global__ __launch_bounds__(256)
void prep_all(const float* __restrict__ gar, const float* __restrict__ cond,
              __nv_bfloat16* __restrict__ inTb, __half* __restrict__ garTh,
              const float* __restrict__ W1, __nv_bfloat16* __restrict__ wb1,
              const float* __restrict__ W2, __nv_bfloat16* __restrict__ wb2,
              const float* __restrict__ W3, __nv_bfloat16* __restrict__ wb3,
              const float* __restrict__ W4, __nv_bfloat16* __restrict__ wb4) {
    if (blockIdx.x < 2048) {
        __shared__ float tile[32][33];
        int tx = threadIdx.x & 31;
        int ty = threadIdx.x >> 5;
        int p0 = (blockIdx.x & 127) * 32;
        int c0 = (blockIdx.x >> 7) * 32;
        for (int i = ty; i < 32; i += 8) {
            int c = c0 + i;
            const float* src = (c < 256) ? (gar + (size_t)c * NP)
                                         : (cond + (size_t)(c - 256) * NP);
            tile[i][tx] = src[p0 + tx];
        }
        __syncthreads();
        for (int i = ty; i < 32; i += 8) {
            float v = tile[tx][i];
            int pix = p0 + i, c = c0 + tx;
            inTb[(size_t)pix * 512 + c] = __float2bfloat16_rn(v);
            if (c0 < 256)
                garTh[(size_t)pix * 256 + c] = __float2half_rn(v);
        }
    } else {
        size_t tidg = (size_t)(blockIdx.x - 2048) * 256 + threadIdx.x;
        size_t nt   = (size_t)2752 * 256;
        wb_region(W1, wb1, 512, 512, 128, 128, tidg, nt);
        wb_region(W2, wb2, 128, 128,  64,  64, tidg, nt);
        wb_region(W3, wb3,  64,  64,  32,  32, tidg, nt);
        wb_region(W4, wb4,  32,  64,  18,  32, tidg, nt);
    }
}

// ---------------------------------------------------------------------------
// bf16 band-reuse implicit-GEMM 3x3 conv. 128 threads = 4 warps (2M x 2N).
// CTA: (ROWS*64) px  x  COUT_CTA couts (cout-split via blockIdx.y).
// Single-buffered band (ROWS+2 rows x 66 cols x 64 cin), reloaded at cin-
// chunk boundaries behind a barrier; B tap-chunks double-buffered, one
// barrier per chunk, next chunk's cp.async overlaps current chunk's MMAs.
//   in:  [g][4096][CIN] bf16 (gstride elems between groups; 0 => shared)
//   OUT_MODE 0: bf16 out[g][pix][OUT_STRIDE] (+coff); 1: fp32 out[g][m][NP].
// ---------------------------------------------------------------------------
template<int CIN, int COUT_TOT, int COUT_CTA, int COUT_REAL, int OUT_STRIDE,
         int ROWS, bool RELU, int OUT_MODE, int MINB>
__global__ __launch_bounds__(128, MINB)
void mconv(const __nv_bfloat16* __restrict__ in, size_t gstride,
           const __nv_bfloat16* __restrict__ Wb, const float* __restrict__ bias,
           void* __restrict__ outv) {
    constexpr int K      = CIN * 9;
    constexpr int NCC    = CIN / 64;
    constexpr int TOT    = NCC * 9;
    constexpr int WN     = COUT_CTA / 2;
    constexpr int NTT    = WN / 8;
    constexpr int MT     = (ROWS == 2) ? 4 : 2;
    constexpr int BPIX   = (ROWS + 2) * 66;
    constexpr int BSTAGE = BPIX * 128;
    constexpr int BBS    = COUT_CTA * 128;
    constexpr int SPLIT  = COUT_TOT / COUT_CTA;

    extern __shared__ char sm[];
    uint32_t base = (smem_u32(sm) + 1023u) & ~1023u;

    const int tid  = threadIdx.x;
    const int warp = tid >> 5;
    const int lane = tid & 31;
    const int lq   = lane >> 2;
    const int lc   = lane & 3;
    const int wm   = warp & 1;
    const int wn   = warp >> 1;
    const int tile = blockIdx.x;
    const int g    = blockIdx.y / SPLIT;
    const int coff = (blockIdx.y % SPLIT) * COUT_CTA;
    const int y0   = tile * ROWS - 1;

    const __nv_bfloat16* src = in + (size_t)g * gstride;
    const __nv_bfloat16* wg  = Wb + ((size_t)g * COUT_TOT + coff) * K;

    const uint32_t bandBase = base;
    const uint32_t bbBase   = base + BSTAGE;

    float acc[MT][NTT][4];
    #pragma unroll
    for (int i = 0; i < MT; i++)
        #pragma unroll
        for (int j = 0; j < NTT; j++)
            #pragma unroll
            for (int q = 0; q < 4; q++) acc[i][j][q] = 0.f;

    auto band_load = [&](int cc) {
        int c0 = cc * 64;
        for (int it = tid; it < BPIX * 8; it += 128) {
            int bp = it >> 3, seg = it & 7;
            int br = bp / 66;
            int col = bp - br * 66;
            int y = y0 + br, x = col - 1;
            bool ok = ((unsigned)y < 64u) & ((unsigned)x < 64u);
            int pix = ok ? (y * 64 + x) : 0;
            const __nv_bfloat16* gp = src + (size_t)pix * CIN + c0 + seg * 8;
            cp16(bandBase + (uint32_t)(bp * 128 + ((seg * 16) ^ ((bp & 7) * 16))), gp, ok);
        }
    };
    auto b_load = [&](int kc, int stage) {
        int cc = kc / 9;
        int koff = (kc - cc * 9) * CIN + cc * 64;
        for (int it = tid; it < COUT_CTA * 8; it += 128) {
            int m = it >> 3, seg = it & 7;
            const __nv_bfloat16* gp = wg + (size_t)m * K + koff + seg * 8;
            cp16(bbBase + stage * BBS
                 + (uint32_t)(m * 128 + ((seg * 16) ^ ((m & 7) * 16))), gp, true);
        }
    };

    // lane-constant ldmatrix address components (A fragments)
    const int amat  = lane >> 3;
    const int aroff = (lane & 7) + (amat & 1) * 8;
    const int akb   = (amat >> 1) * 16;

    auto compute = [&](int tap, int bstage) {
        int r = tap / 3, s = tap - 3 * (tap / 3);
        int bbase0 = r * 66 + s + ((ROWS == 2) ? wm * 66 : wm * 32);
        uint32_t aS = bandBase;
        uint32_t bS = bbBase + bstage * BBS;
        #pragma unroll
        for (int seg = 0; seg < 4; seg++) {
            uint32_t af[MT][4];
            #pragma unroll
            for (int mt = 0; mt < MT; mt++) {
                int bp = bbase0 + mt * 16 + aroff;
                uint32_t addr = aS + (uint32_t)(bp * 128 + ((seg * 32 + akb) ^ ((bp & 7) * 16)));
                ldsm4(af[mt], addr);
            }
            uint32_t bf[NTT][2];
            #pragma unroll
            for (int ntp = 0; ntp < NTT / 2; ntp++) {
                int n = wn * WN + (ntp * 2 + (lane >> 4)) * 8 + (lane & 7);
                int kb = ((lane >> 3) & 1) * 16;
                uint32_t addr = bS + (uint32_t)(n * 128 + ((seg * 32 + kb) ^ ((n & 7) * 16)));
                uint32_t tmp[4];
                ldsm4(tmp, addr);
                bf[2 * ntp][0] = tmp[0]; bf[2 * ntp][1] = tmp[1];
                bf[2 * ntp + 1][0] = tmp[2]; bf[2 * ntp + 1][1] = tmp[3];
            }
            #pragma unroll
            for (int mt = 0; mt < MT; mt++)
                #pragma unroll
                for (int nt = 0; nt < NTT; nt++)
                    mma_bf16(acc[mt][nt], af[mt], bf[nt]);
        }
    };

    band_load(0); b_load(0, 0); CP_COMMIT();
    for (int kc = 0; kc < TOT; kc++) {
        CP_WAIT(0);
        __syncthreads();                       // chunk kc visible to all warps
        int nb = kc + 1;
        bool bandNext = (nb < TOT) && (nb % 9 == 0);
        if (nb < TOT && !bandNext) {           // overlap next B with compute
            b_load(nb, nb & 1);
            CP_COMMIT();
        }
        int cc = kc / 9, tap = kc - cc * 9;
        compute(tap, kc & 1);
        if (bandNext) {                        // band reload behind barrier
            __syncthreads();                   // all warps done reading band
            band_load(nb / 9);
            b_load(nb, nb & 1);
            CP_COMMIT();
        }
    }

    // Epilogue: bias + lrelu, store.
    #pragma unroll
    for (int mt = 0; mt < MT; mt++) {
        int prow = tile * (ROWS * 64) + wm * ((ROWS == 2) ? 64 : 32) + mt * 16 + lq;
        #pragma unroll
        for (int nt = 0; nt < NTT; nt++) {
            int n0  = wn * WN + nt * 8 + lc * 2;
            int ng  = coff + n0;
            float b0 = (ng     < COUT_REAL) ? bias[g * COUT_REAL + ng]     : 0.f;
            float b1 = (ng + 1 < COUT_REAL) ? bias[g * COUT_REAL + ng + 1] : 0.f;
            #pragma unroll
            for (int h = 0; h < 2; h++) {
                int p = prow + h * 8;
                float v0 = acc[mt][nt][h * 2]     + b0;
                float v1 = acc[mt][nt][h * 2 + 1] + b1;
                if (RELU) {
                    v0 = (v0 >= 0.f) ? v0 : 0.1f * v0;
                    v1 = (v1 >= 0.f) ? v1 : 0.1f * v1;
                }
                if (OUT_MODE == 0) {
                    __nv_bfloat16* ob = (__nv_bfloat16*)outv;
                    __nv_bfloat162 pr;
                    pr.x = __float2bfloat16_rn(v0);
                    pr.y = __float2bfloat16_rn(v1);
                    *(__nv_bfloat162*)(ob + ((size_t)g * NP + p) * OUT_STRIDE + ng) = pr;
                } else {
                    float* of = (float*)outv;
                    if (ng < COUT_REAL)
                        of[(size_t)(g * COUT_REAL + ng) * NP + p] = v0;
                    if (ng + 1 < COUT_REAL)
                        of[(size_t)(g * COUT_REAL + ng + 1) * NP + p] = v1;
                }
            }
        }
    }
}

// ---------------------------------------------------------------------------
// Final warp/sample kernel with tap dedup (unchanged).
// ---------------------------------------------------------------------------
__global__ __launch_bounds__(256)
void warp_kernel(const float* __restrict__ oa, const __half* __restrict__ garTh,
                 const float* __restrict__ mask, float* __restrict__ out) {
    __shared__ int   sO[4][192];
    __shared__ float sA[4][192];
    __shared__ int   sPosC[4][8][24];
    __shared__ float sWC[4][8][24];
    __shared__ int   sCnt[4][8];

    const int pix0 = blockIdx.x * 4;
    const int tt = threadIdx.x;

    if (tt < 24) {
        int p = tt / 6, k = tt - (tt / 6) * 6;
        int pix = pix0 + p;
        float fx = (float)(pix & 63);
        float fy = (float)(pix >> 6);
        float lg[8], ox[8], oy[8];
        #pragma unroll
        for (int g = 0; g < 8; g++) {
            const float* base = oa + (size_t)g * 18 * NP + pix;
            lg[g] = base[(12 + k) * NP];
            ox[g] = base[(2 * k) * NP];
            oy[g] = base[(2 * k + 1) * NP];
        }
        float m = lg[0];
        #pragma unroll
        for (int g = 1; g < 8; g++) m = fmaxf(m, lg[g]);
        float s = 0.f;
        #pragma unroll
        for (int g = 0; g < 8; g++) { lg[g] = expf(lg[g] - m); s += lg[g]; }
        float inv = 1.f / s;
        #pragma unroll
        for (int g = 0; g < 8; g++) {
            float attn = lg[g] * inv;
            float xs = fminf(fmaxf((fx + ox[g]) * (64.0f / 63.0f) - 0.5f, 0.f), 63.f);
            float ys = fminf(fmaxf((fy + oy[g]) * (64.0f / 63.0f) - 0.5f, 0.f), 63.f);
            float x0f = floorf(xs), y0f = floorf(ys);
            float wx = xs - x0f, wy = ys - y0f;
            int x0 = (int)x0f, y0 = (int)y0f;
            int x1 = min(x0 + 1, 63), y1 = min(y0 + 1, 63);
            int q = (p * 6 + k) * 8 + g;
            sO[0][q] = (y0 * 64 + x0) * 256;
            sO[1][q] = (y0 * 64 + x1) * 256;
            sO[2][q] = (y1 * 64 + x0) * 256;
            sO[3][q] = (y1 * 64 + x1) * 256;
            sA[0][q] = attn * (1.f - wy) * (1.f - wx);
            sA[1][q] = attn * (1.f - wy) * wx;
            sA[2][q] = attn * wy * (1.f - wx);
            sA[3][q] = attn * wy * wx;
        }
    }
    __syncthreads();

    if (tt < 32) {
        int p = tt >> 3, g = tt & 7;
        int cnt = 0;
        for (int k = 0; k < 6; k++) {
            int qbase = (p * 6 + k) * 8 + g;
            #pragma unroll
            for (int q = 0; q < 4; q++) {
                int   po = sO[q][qbase];
                float ww = sA[q][qbase];
                int j = 0;
                for (; j < cnt; j++) {
                    if (sPosC[p][g][j] == po) { sWC[p][g][j] += ww; break; }
                }
                if (j == cnt) { sPosC[p][g][cnt] = po; sWC[p][g][cnt] = ww; cnt++; }
            }
        }
        sCnt[p][g] = cnt;
    }
    __syncthreads();

    const int c = tt;  // channel
    float mk[8];
    #pragma unroll
    for (int g = 0; g < 8; g++) mk[g] = mask[g * 256 + c];

    for (int p = 0; p < 4; p++) {
        float accP = 0.f;
        #pragma unroll
        for (int g = 0; g < 8; g++) {
            int cnt = sCnt[p][g];      // uniform across block
            float accG = 0.f;
            for (int j = 0; j < cnt; j++)
                accG += sWC[p][g][j] * __half2float(garTh[sPosC[p][g][j] + c]);
            accP += accG * mk[g];
        }
        out[(size_t)c * NP + pix0 + p] = accP;
    }
}

// ---------------------------------------------------------------------------
extern "C" void kernel_launch(void* const* d_in, const int* in_sizes, int n_in,
                              void* d_out, int out_size) {
    const float* gar  = (const float*)d_in[0];
    const float* cond = (const float*)d_in[1];
    const float* mask = (const float*)d_in[2];
    const float* W1   = (const float*)d_in[3];
    const float* b1   = (const float*)d_in[4];
    const float* W2   = (const float*)d_in[5];
    const float* b2   = (const float*)d_in[6];
    const float* W3   = (const float*)d_in[7];
    const float* b3   = (const float*)d_in[8];
    const float* W4   = (const float*)d_in[9];
    const float* b4   = (const float*)d_in[10];
    float* out = (float*)d_out;

    float* S = nullptr;
    cudaGetSymbolAddress((void**)&S, g_scratch);
    __nv_bfloat16* inTb  = (__nv_bfloat16*)(S + OFF_INT);
    __half*        garTh = (__half*)       (S + OFF_GART);
    __nv_bfloat16* wb1   = (__nv_bfloat16*)(S + OFF_WB1);
    __nv_bfloat16* wb2   = (__nv_bfloat16*)(S + OFF_WB2);
    __nv_bfloat16* wb3   = (__nv_bfloat16*)(S + OFF_WB3);
    __nv_bfloat16* wb4   = (__nv_bfloat16*)(S + OFF_WB4);
    __nv_bfloat16* h1    = (__nv_bfloat16*)(S + OFF_H1);
    __nv_bfloat16* h2    = (__nv_bfloat16*)(S + OFF_H2);
    __nv_bfloat16* h3    = (__nv_bfloat16*)(S + OFF_H3);
    float*         oa    = S + OFF_OA;

    // dynamic smem: 1 band + 2 B stages (+1KB align slack)
    const int SM1  = 264 * 128 + 2 * 64 * 128 + 1024;  // 51200  -> occ 4
    const int SM2  = 264 * 128 + 2 * 32 * 128 + 1024;  // 43008  -> occ 5
    const int SM34 = 198 * 128 + 2 * 32 * 128 + 1024;  // 34560  -> occ 6

    cudaFuncSetAttribute(mconv<512,128,64,128,128,2,true ,0,4>, cudaFuncAttributeMaxDynamicSharedMemorySize, SM1);
    cudaFuncSetAttribute(mconv<128, 64,32, 64, 64,2,true ,0,5>, cudaFuncAttributeMaxDynamicSharedMemorySize, SM2);
    cudaFuncSetAttribute(mconv< 64, 32,32, 32, 64,1,true ,0,6>, cudaFuncAttributeMaxDynamicSharedMemorySize, SM34);
    cudaFuncSetAttribute(mconv< 64, 32,32, 18,  1,1,false,1,6>, cudaFuncAttributeMaxDynamicSharedMemorySize, SM34);

    prep_all<<<2048 + 2752, 256>>>(gar, cond, inTb, garTh,
                                   W1, wb1, W2, wb2, W3, wb3, W4, wb4);

    mconv<512,128,64,128,128,2,true ,0,4><<<dim3(32, 16), 128, SM1 >>>(inTb, 0,              wb1, b1, h1);
    mconv<128, 64,32, 64, 64,2,true ,0,5><<<dim3(32, 16), 128, SM2 >>>(h1, (size_t)NP * 128, wb2, b2, h2);
    mconv< 64, 32,32, 32, 64,1,true ,0,6><<<dim3(64,  8), 128, SM34>>>(h2, (size_t)NP * 64,  wb3, b3, h3);
    mconv< 64, 32,32, 18,  1,1,false,1,6><<<dim3(64,  8), 128, SM34>>>(h3, (size_t)NP * 64,  wb4, b4, oa);

    warp_kernel<<<NP / 4, 256>>>(oa, garTh, mask, out);
}